// round 3
// baseline (speedup 1.0000x reference)
#include <cuda_runtime.h>
#include <math.h>

#define B_      4
#define L_      4096
#define DIM_    1024
#define STATE_  16
#define NC_     128             // chunks per batch
#define CHUNK_  (L_ / NC_)      // 32
#define WARM_   192             // contraction ~0.956/step -> ~2e-5 residual in y

// ---------------- scratch (no allocations allowed) ----------------
__device__ float g_scale;                       // spectral-norm scale for A
__device__ float g_dt[B_ * L_];                 // dt[b][t]
__device__ float g_bx[B_ * L_ * STATE_];        // Bx[b][t][i]
__device__ float g_states[B_ * L_ * STATE_];    // normalized states s[b][t][i]

// packed f32x2 FMA: {cx,cy} += {ax,ay} * {bx,by}  (single FFMA2, 2x fma rate)
__device__ __forceinline__ void ffma2(float& cx, float& cy,
                                      float ax, float ay, float bx, float by) {
    asm("{\n\t"
        ".reg .b64 ra, rb, rc;\n\t"
        "mov.b64 ra, {%2, %3};\n\t"
        "mov.b64 rb, {%4, %5};\n\t"
        "mov.b64 rc, {%0, %1};\n\t"
        "fma.rn.f32x2 rc, ra, rb, rc;\n\t"
        "mov.b64 {%0, %1}, rc;\n\t"
        "}"
        : "+f"(cx), "+f"(cy)
        : "f"(ax), "f"(ay), "f"(bx), "f"(by));
}

// =================================================================
// K0: spectral scale. Exact fast path: sigma_max <= ||A||_F, so if
// ||A||_F <= 0.99 then scale == 1 exactly. Fallback: power iteration.
// =================================================================
__global__ void k0_scale(const float* __restrict__ A) {
    __shared__ float sA[256];
    __shared__ float red[256];
    int t = threadIdx.x;
    float a = A[t];
    sA[t] = a;
    red[t] = a * a;
    __syncthreads();
    for (int s = 128; s > 0; s >>= 1) {
        if (t < s) red[t] += red[t + s];
        __syncthreads();
    }
    if (t == 0) {
        float scale = 1.0f;
        if (red[0] > 0.9801f) {   // Frobenius bound fails -> compute sigma_max
            float v[16];
            #pragma unroll
            for (int k = 0; k < 16; k++) v[k] = 1.0f;
            for (int it = 0; it < 400; ++it) {
                float u[16];
                for (int r = 0; r < 16; r++) {
                    float acc = 0.f;
                    for (int c = 0; c < 16; c++) acc = fmaf(sA[r * 16 + c], v[c], acc);
                    u[r] = acc;
                }
                float w2[16]; float nn = 0.f;
                for (int c = 0; c < 16; c++) {
                    float acc = 0.f;
                    for (int r = 0; r < 16; r++) acc = fmaf(sA[r * 16 + c], u[r], acc);
                    w2[c] = acc; nn += acc * acc;
                }
                float inv = rsqrtf(fmaxf(nn, 1e-30f));
                for (int c = 0; c < 16; c++) v[c] = w2[c] * inv;
            }
            float sig2 = 0.f;
            for (int r = 0; r < 16; r++) {
                float acc = 0.f;
                for (int c = 0; c < 16; c++) acc = fmaf(sA[r * 16 + c], v[c], acc);
                sig2 += acc * acc;
            }
            float sigma = sqrtf(sig2);
            if (sigma > 0.99f) scale = 0.99f / sigma;
        }
        g_scale = scale;
    }
}

// =================================================================
// K1: per-row projections, TWO rows per warp (W_B stream shared),
// inner products via packed FFMA2.
// =================================================================
__global__ void __launch_bounds__(256) k1_proj(const float* __restrict__ x,
                                               const float* __restrict__ W_B,
                                               const float* __restrict__ dt_w,
                                               const float* __restrict__ dt_b) {
    int warp = (blockIdx.x * blockDim.x + threadIdx.x) >> 5;
    int lane = threadIdx.x & 31;
    int r0 = warp * 2;
    if (r0 >= B_ * L_) return;

    const float4* xr0 = reinterpret_cast<const float4*>(x + (size_t)r0 * DIM_) + lane;
    const float4* xr1 = reinterpret_cast<const float4*>(x + (size_t)(r0 + 1) * DIM_) + lane;
    float4 xv0[8], xv1[8];
    #pragma unroll
    for (int k = 0; k < 8; k++) { xv0[k] = xr0[k * 32]; xv1[k] = xr1[k * 32]; }

    float acc0[17], acc1[17];
    #pragma unroll
    for (int i = 0; i < 17; i++) {
        const float* wrow = (i < 16) ? (W_B + (size_t)i * DIM_) : dt_w;
        const float4* wr = reinterpret_cast<const float4*>(wrow) + lane;
        float a0x = 0.f, a0y = 0.f, a1x = 0.f, a1y = 0.f;
        float b0x = 0.f, b0y = 0.f, b1x = 0.f, b1y = 0.f;
        #pragma unroll
        for (int k = 0; k < 8; k++) {
            float4 w4 = wr[k * 32];
            ffma2(a0x, a0y, xv0[k].x, xv0[k].y, w4.x, w4.y);
            ffma2(a1x, a1y, xv0[k].z, xv0[k].w, w4.z, w4.w);
            ffma2(b0x, b0y, xv1[k].x, xv1[k].y, w4.x, w4.y);
            ffma2(b1x, b1y, xv1[k].z, xv1[k].w, w4.z, w4.w);
        }
        acc0[i] = (a0x + a0y) + (a1x + a1y);
        acc1[i] = (b0x + b0y) + (b1x + b1y);
    }

    #pragma unroll
    for (int m = 16; m >= 1; m >>= 1) {
        #pragma unroll
        for (int i = 0; i < 17; i++) {
            acc0[i] += __shfl_xor_sync(0xffffffffu, acc0[i], m);
            acc1[i] += __shfl_xor_sync(0xffffffffu, acc1[i], m);
        }
    }

    if (lane == 0) {
        float dtb = dt_b[0];
        float4* bo0 = reinterpret_cast<float4*>(g_bx + (size_t)r0 * STATE_);
        bo0[0] = make_float4(acc0[0],  acc0[1],  acc0[2],  acc0[3]);
        bo0[1] = make_float4(acc0[4],  acc0[5],  acc0[6],  acc0[7]);
        bo0[2] = make_float4(acc0[8],  acc0[9],  acc0[10], acc0[11]);
        bo0[3] = make_float4(acc0[12], acc0[13], acc0[14], acc0[15]);
        float z0  = acc0[16] + dtb;
        float sp0 = (z0 > 15.f) ? z0 : log1pf(expf(z0));
        g_dt[r0] = fminf(fmaxf(sp0, 0.001f), 0.1f);

        float4* bo1 = reinterpret_cast<float4*>(g_bx + (size_t)(r0 + 1) * STATE_);
        bo1[0] = make_float4(acc1[0],  acc1[1],  acc1[2],  acc1[3]);
        bo1[1] = make_float4(acc1[4],  acc1[5],  acc1[6],  acc1[7]);
        bo1[2] = make_float4(acc1[8],  acc1[9],  acc1[10], acc1[11]);
        bo1[3] = make_float4(acc1[12], acc1[13], acc1[14], acc1[15]);
        float z1  = acc1[16] + dtb;
        float sp1 = (z1 > 15.f) ? z1 : log1pf(expf(z1));
        g_dt[r0 + 1] = fminf(fmaxf(sp1, 0.001f), 0.1f);
    }
}

// =================================================================
// K2: chunked sequential scan with warm-up (192 steps, chunks of 32).
// One 16-lane group per (batch, chunk); 2 groups per warp (same chunk,
// different batch -> fully convergent). mean/var come free from the
// same shfl broadcast that feeds the matvec.
// =================================================================
__global__ void __launch_bounds__(32) k2_scan(const float* __restrict__ A,
                                              const float* __restrict__ state_in,
                                              const float* __restrict__ ln_w,
                                              const float* __restrict__ ln_b) {
    const unsigned FULL = 0xffffffffu;
    int lane = threadIdx.x;
    int seg  = lane >> 4;
    int i    = lane & 15;
    int gidx = blockIdx.x * 2 + seg;  // 0..511
    int b     = gidx & 3;
    int chunk = gidx >> 2;            // same across the warp's two segs
    int cs   = chunk * CHUNK_;
    int ws   = cs - WARM_; if (ws < 0) ws = 0;
    int tend = cs + CHUNK_;

    float scale = g_scale;

    float w_[16], b_[16];
    #pragma unroll
    for (int j = 0; j < 16; j += 4) {
        float4 t4 = *reinterpret_cast<const float4*>(ln_w + j);
        w_[j] = t4.x; w_[j + 1] = t4.y; w_[j + 2] = t4.z; w_[j + 3] = t4.w;
        float4 u4 = *reinterpret_cast<const float4*>(ln_b + j);
        b_[j] = u4.x; b_[j + 1] = u4.y; b_[j + 2] = u4.z; b_[j + 3] = u4.w;
    }
    float an[16], ap[16];
    #pragma unroll
    for (int j = 0; j < 16; j += 4) {
        float4 a4 = *reinterpret_cast<const float4*>(A + i * 16 + j);
        an[j] = a4.x * scale; an[j + 1] = a4.y * scale;
        an[j + 2] = a4.z * scale; an[j + 3] = a4.w * scale;
    }
    float aw1 = 0.f, ab = 0.f;
    #pragma unroll
    for (int j = 0; j < 16; j++) {
        ap[j] = an[j] * w_[j];
        aw1  += ap[j];
        ab    = fmaf(an[j], b_[j], ab);
    }
    float wi = ln_w[i];
    float bi = ln_b[i];

    const float* dtp = g_dt + (size_t)b * L_;
    const float* bxp = g_bx + (size_t)b * L_ * STATE_ + i;
    float*       stp = g_states + (size_t)b * L_ * STATE_ + i;

    // prologue: h_ws = s0 + dt[ws]*(An s0) + bx[ws]
    float s0 = (ws == 0) ? state_in[b * STATE_ + i] : 0.f;
    float p0 = 0.f, p1 = 0.f, p2 = 0.f, p3 = 0.f;
    #pragma unroll
    for (int j = 0; j < 16; j += 4) {
        p0 = fmaf(an[j],     __shfl_sync(FULL, s0, j,     16), p0);
        p1 = fmaf(an[j + 1], __shfl_sync(FULL, s0, j + 1, 16), p1);
        p2 = fmaf(an[j + 2], __shfl_sync(FULL, s0, j + 2, 16), p2);
        p3 = fmaf(an[j + 3], __shfl_sync(FULL, s0, j + 3, 16), p3);
    }
    float g0 = (p0 + p1) + (p2 + p3);
    float h = fmaf(dtp[ws], g0, s0) + bxp[(size_t)ws * STATE_];

    int tp1 = ws + 1; if (tp1 > L_ - 1) tp1 = L_ - 1;
    int tp2 = ws + 2; if (tp2 > L_ - 1) tp2 = L_ - 1;
    int tp3 = ws + 3; if (tp3 > L_ - 1) tp3 = L_ - 1;
    float dtA = dtp[tp1], bxA = bxp[(size_t)tp1 * STATE_];
    float dtB = dtp[tp2], bxB = bxp[(size_t)tp2 * STATE_];
    float dtC = dtp[tp3], bxC = bxp[(size_t)tp3 * STATE_];

    for (int t = ws; t < tend; ++t) {
        float hv[16];
        #pragma unroll
        for (int j = 0; j < 16; j++) hv[j] = __shfl_sync(FULL, h, j, 16);

        float m0, m1, m2, m3, u0, u1, q0, q1, q2, q3;
        m0 = ap[0] * hv[0]; m1 = ap[1] * hv[1]; m2 = ap[2] * hv[2]; m3 = ap[3] * hv[3];
        u0 = hv[0] + hv[1]; u1 = hv[2] + hv[3];
        q0 = hv[0] * hv[0]; q1 = hv[1] * hv[1]; q2 = hv[2] * hv[2]; q3 = hv[3] * hv[3];
        #pragma unroll
        for (int j = 4; j < 16; j += 4) {
            m0 = fmaf(ap[j],     hv[j],     m0);
            m1 = fmaf(ap[j + 1], hv[j + 1], m1);
            m2 = fmaf(ap[j + 2], hv[j + 2], m2);
            m3 = fmaf(ap[j + 3], hv[j + 3], m3);
            u0 += hv[j] + hv[j + 1];
            u1 += hv[j + 2] + hv[j + 3];
            q0 = fmaf(hv[j],     hv[j],     q0);
            q1 = fmaf(hv[j + 1], hv[j + 1], q1);
            q2 = fmaf(hv[j + 2], hv[j + 2], q2);
            q3 = fmaf(hv[j + 3], hv[j + 3], q3);
        }
        float g = (m0 + m1) + (m2 + m3);
        float u = u0 + u1;
        float q = (q0 + q1) + (q2 + q3);

        float mu    = u * 0.0625f;
        float var   = fmaf(-mu, mu, q * 0.0625f);
        float alpha = rsqrtf(var + 1e-5f);
        float hm    = h - mu;

        if (t >= cs) stp[(size_t)t * STATE_] = fmaf(alpha * hm, wi, bi);

        float dtn = dtA, bxn = bxA;
        dtA = dtB; bxA = bxB;
        dtB = dtC; bxB = bxC;
        int tn = t + 4; if (tn > L_ - 1) tn = L_ - 1;
        dtC = dtp[tn]; bxC = bxp[(size_t)tn * STATE_];

        float t1 = fmaf(-mu, aw1, g);
        float t2 = fmaf(dtn, t1, hm * wi);
        h = fmaf(alpha, t2, fmaf(dtn, ab, bi) + bxn);
    }
}

// =================================================================
// K3: y = states @ W_C^T + D*x. 32 rows/block (512 blocks), states
// staged via smem (coalesced once, broadcast reads), x prefetched
// 4 rows deep, inner products via packed FFMA2.
// =================================================================
#define K3_ROWS 32

__global__ void __launch_bounds__(256) k3_out(const float* __restrict__ x,
                                              const float* __restrict__ W_C,
                                              const float* __restrict__ D,
                                              float* __restrict__ out,
                                              int write_tail) {
    __shared__ float2 sst[K3_ROWS * 8];   // 32 rows x 16 floats

    int rb = blockIdx.x * K3_ROWS;
    int d  = threadIdx.x * 4;

    // cooperative state stage: 512 floats = 256 float2, one per thread
    {
        const float2* src = reinterpret_cast<const float2*>(g_states + (size_t)rb * STATE_);
        sst[threadIdx.x] = src[threadIdx.x];
    }

    // W_C rows d..d+3 as packed pairs (amortized over 32 rows)
    float2 wc[32];
    const float4* wp = reinterpret_cast<const float4*>(W_C + (size_t)d * STATE_);
    #pragma unroll
    for (int k = 0; k < 16; k++) {
        float4 w4 = wp[k];
        wc[2 * k]     = make_float2(w4.x, w4.y);
        wc[2 * k + 1] = make_float2(w4.z, w4.w);
    }
    float4 dd = *reinterpret_cast<const float4*>(D + d);
    __syncthreads();

    // x pipeline: 4 rows in flight
    float4 xb[4];
    #pragma unroll
    for (int j = 0; j < 4; j++)
        xb[j] = *reinterpret_cast<const float4*>(x + (size_t)(rb + j) * DIM_ + d);

    for (int r0 = 0; r0 < K3_ROWS; r0 += 4) {
        float4 xc[4];
        #pragma unroll
        for (int j = 0; j < 4; j++) xc[j] = xb[j];
        if (r0 + 4 < K3_ROWS) {
            #pragma unroll
            for (int j = 0; j < 4; j++)
                xb[j] = *reinterpret_cast<const float4*>(x + (size_t)(rb + r0 + 4 + j) * DIM_ + d);
        }

        #pragma unroll
        for (int rr = 0; rr < 4; rr++) {
            const float2* s = sst + (r0 + rr) * 8;
            float2 sv[8];
            #pragma unroll
            for (int k = 0; k < 8; k++) sv[k] = s[k];

            float y0x = 0.f, y0y = 0.f, y1x = 0.f, y1y = 0.f;
            float y2x = 0.f, y2y = 0.f, y3x = 0.f, y3y = 0.f;
            #pragma unroll
            for (int k = 0; k < 8; k++) {
                ffma2(y0x, y0y, wc[k].x,      wc[k].y,      sv[k].x, sv[k].y);
                ffma2(y1x, y1y, wc[8 + k].x,  wc[8 + k].y,  sv[k].x, sv[k].y);
                ffma2(y2x, y2y, wc[16 + k].x, wc[16 + k].y, sv[k].x, sv[k].y);
                ffma2(y3x, y3y, wc[24 + k].x, wc[24 + k].y, sv[k].x, sv[k].y);
            }
            float4 y;
            y.x = fmaf(dd.x, xc[rr].x, y0x + y0y);
            y.y = fmaf(dd.y, xc[rr].y, y1x + y1y);
            y.z = fmaf(dd.z, xc[rr].z, y2x + y2y);
            y.w = fmaf(dd.w, xc[rr].w, y3x + y3y);
            *reinterpret_cast<float4*>(out + (size_t)(rb + r0 + rr) * DIM_ + d) = y;
        }
    }

    // new_state = states[:, L-1, :]
    if (write_tail && blockIdx.x == 0 && threadIdx.x < B_ * STATE_) {
        int bb = threadIdx.x >> 4, ii = threadIdx.x & 15;
        out[(size_t)B_ * L_ * DIM_ + threadIdx.x] =
            g_states[((size_t)bb * L_ + (L_ - 1)) * STATE_ + ii];
    }
}

// =================================================================
extern "C" void kernel_launch(void* const* d_in, const int* in_sizes, int n_in,
                              void* d_out, int out_size) {
    const float* x     = (const float*)d_in[0];
    const float* state = (const float*)d_in[1];
    const float* A     = (const float*)d_in[2];
    const float* W_B   = (const float*)d_in[3];
    const float* W_C   = (const float*)d_in[4];
    const float* D     = (const float*)d_in[5];
    const float* dt_w  = (const float*)d_in[6];
    const float* dt_b  = (const float*)d_in[7];
    const float* ln_w  = (const float*)d_in[8];
    const float* ln_b  = (const float*)d_in[9];
    float* out = (float*)d_out;

    k0_scale<<<1, 256>>>(A);
    k1_proj<<<(B_ * L_ / 2 * 32) / 256, 256>>>(x, W_B, dt_w, dt_b);      // 1024 blocks
    k2_scan<<<(B_ * NC_) / 2, 32>>>(A, state, ln_w, ln_b);               // 256 blocks
    int tail = (out_size >= B_ * L_ * DIM_ + B_ * STATE_) ? 1 : 0;
    k3_out<<<(B_ * L_) / K3_ROWS, 256>>>(x, W_C, D, out, tail);          // 512 blocks
}